// round 11
// baseline (speedup 1.0000x reference)
#include <cuda_runtime.h>
#include <cstdint>

// Problem constants
#define B_   16
#define H_   224
#define W_   224
#define C_   64
#define HO_  112
#define WO_  112
#define NPATCH (HO_ * WO_)          // 12544 per image
#define TOTPATCH (B_ * NPATCH)      // 200704
#define KSEL 1254
#define KCAP 1280                   // per-image kept-list capacity (tie slack)
#define NHBIN 2048

// Scratch (__device__ globals, no allocs). Zero-initialized at module load;
// g_hist is re-zeroed by scatter_kernel each replay (stream-ordered before
// the next replay's conv), so every replay sees identical state.
__device__ float    g_scores[TOTPATCH];     // conv outputs
__device__ unsigned g_hist[B_ * NHBIN];     // per-image round-1 histogram
__device__ unsigned g_thr[B_];              // per-image K-th orderable key
__device__ unsigned g_cand[TOTPATCH];       // boundary-bin candidate keys
__device__ int      g_cidx[TOTPATCH];       // boundary-bin candidate indices
__device__ int      g_kidx[B_ * KCAP];      // kept patch index (within image)
__device__ float    g_kval[B_ * KCAP];      // kept gate value
__device__ unsigned g_kcnt[B_];             // kept count per image

__device__ __forceinline__ unsigned float_orderable(float f)
{
    unsigned u = __float_as_uint(f);
    return u ^ ((u & 0x80000000u) ? 0xFFFFFFFFu : 0x80000000u);
}

// ---------------------------------------------------------------------------
// Kernel 1: fused conv + zero-fill + round-1 histogram. One warp per EIGHT
// horizontally adjacent patches: reads its 8 KB x tile (conv scores), streams
// 8 KB of zeros into y (scatter overwrites kept patches later), and lane 0
// feeds the per-image top-11-bit histogram via global atomics.
// ---------------------------------------------------------------------------
__global__ void __launch_bounds__(256, 6)
conv_zero_kernel(const float* __restrict__ x,
                 const float* __restrict__ wk,
                 float* __restrict__ y)
{
    const unsigned warp = (blockIdx.x * blockDim.x + threadIdx.x) >> 5;
    const int lane = threadIdx.x & 31;
    const unsigned p0 = warp * 8;               // first patch of this group
    if (p0 >= TOTPATCH) return;

    const int b   = p0 / NPATCH;
    const int rem = p0 % NPATCH;
    const int ho  = rem / WO_;
    const int wo  = rem % WO_;                  // multiple of 8

    const size_t base = (((size_t)b * H_ + 2 * ho) * W_ + 2 * wo) * C_;
    const float4* xr = reinterpret_cast<const float4*>(x + base);
    float4*       yr = reinterpret_cast<float4*>(y + base);
    const float4* wr = reinterpret_cast<const float4*>(wk);
    const int rs = W_ * (C_ / 4);               // row stride in float4

    const float4 w0 = __ldg(&wr[lane]);
    const float4 w1 = __ldg(&wr[32 + lane]);

    // Issue all 16 loads first (max MLP), then the 16 zero stores.
    float4 a0[8], a1[8];
    #pragma unroll
    for (int j = 0; j < 8; ++j) a0[j] = __ldcs(&xr[32 * j + lane]);
    #pragma unroll
    for (int j = 0; j < 8; ++j) a1[j] = __ldcs(&xr[rs + 32 * j + lane]);

    const float4 z = make_float4(0.f, 0.f, 0.f, 0.f);
    #pragma unroll
    for (int j = 0; j < 8; ++j) __stcs(&yr[32 * j + lane], z);
    #pragma unroll
    for (int j = 0; j < 8; ++j) __stcs(&yr[rs + 32 * j + lane], z);

    float s[8];
    #pragma unroll
    for (int j = 0; j < 8; ++j) {
        s[j] = a0[j].x * w0.x + a0[j].y * w0.y + a0[j].z * w0.z + a0[j].w * w0.w
             + a1[j].x * w1.x + a1[j].y * w1.y + a1[j].z * w1.z + a1[j].w * w1.w;
    }

    #pragma unroll
    for (int j = 0; j < 8; ++j) {
        #pragma unroll
        for (int off = 16; off; off >>= 1)
            s[j] += __shfl_down_sync(0xffffffffu, s[j], off);
    }

    if (lane == 0) {
        *reinterpret_cast<float4*>(&g_scores[p0])     = make_float4(s[0], s[1], s[2], s[3]);
        *reinterpret_cast<float4*>(&g_scores[p0 + 4]) = make_float4(s[4], s[5], s[6], s[7]);
        #pragma unroll
        for (int j = 0; j < 8; ++j)
            atomicAdd(&g_hist[b * NHBIN + (float_orderable(s[j]) >> 21)], 1u);
    }
}

// ---------------------------------------------------------------------------
// Kernel 2: per-image K-th-largest threshold via radix select + kept-list
// compaction. Round 1 histogram comes precomputed from conv_zero (g_hist),
// so only ONE full 800 KB scan remains (the compaction pass). Loops with
// warp-collective emit_kept are padded to a multiple of blockDim.x.
// ---------------------------------------------------------------------------

// All 32 lanes of the warp MUST call this (kept=false for inactive work).
__device__ __forceinline__ void emit_kept(int b, unsigned* s_kcnt,
                                          int lane, bool kept, int idx, float val)
{
    const unsigned m = __ballot_sync(0xffffffffu, kept);
    if (kept) {
        const int leader = __ffs(m) - 1;
        unsigned basep = 0;
        if (lane == leader) basep = atomicAdd(s_kcnt, (unsigned)__popc(m));
        basep = __shfl_sync(m, basep, leader);
        const unsigned slot = basep + __popc(m & ((1u << lane) - 1u));
        if (slot < KCAP) {
            g_kidx[b * KCAP + slot] = idx;
            g_kval[b * KCAP + slot] = val;
        }
    }
}

__global__ void select_thr_kernel()
{
    __shared__ unsigned hist[2048];
    __shared__ unsigned chunk[64];
    __shared__ unsigned s_prefix, s_kth, s_cnt, s_kcnt;

    const int b    = blockIdx.x;
    const int tid  = threadIdx.x;
    const int lane = tid & 31;
    const unsigned bdim = blockDim.x;
    const float* gb = g_scores + (size_t)b * NPATCH;
    unsigned* cand = g_cand + (size_t)b * NPATCH;
    int*      cidx = g_cidx + (size_t)b * NPATCH;

    if (tid == 0) { s_cnt = 0u; s_kcnt = 0u; }

    // ---- Round 1: read precomputed histogram (bits [21..31]) ----
    for (int i = tid; i < 2048; i += bdim) hist[i] = g_hist[b * NHBIN + i];
    __syncthreads();
    if (tid < 64) {
        unsigned s = 0;
        #pragma unroll 4
        for (int i = 0; i < 32; ++i) s += hist[tid * 32 + i];
        chunk[tid] = s;
    }
    __syncthreads();
    if (tid == 0) {
        unsigned kth = KSEL;
        int c = 63;
        for (; c > 0; --c) { if (kth <= chunk[c]) break; kth -= chunk[c]; }
        const int base = c * 32;
        int d = 31;
        for (; d > 0; --d) { if (kth <= hist[base + d]) break; kth -= hist[base + d]; }
        s_prefix = (unsigned)(base + d) << 21;
        s_kth = kth;
    }
    __syncthreads();
    const unsigned top = s_prefix >> 21;

    // ---- Compaction pass: definite keeps + boundary candidates ----
    {
        const unsigned nloop = ((NPATCH + bdim - 1) / bdim) * bdim;
        for (unsigned i = tid; i < nloop; i += bdim) {
            const bool valid = (i < NPATCH);
            const float f = valid ? gb[i] : 0.0f;
            const unsigned u = float_orderable(f);
            const unsigned bin = u >> 21;
            emit_kept(b, &s_kcnt, lane, valid && (bin > top), (int)i, f);
            if (valid && bin == top) {
                unsigned idx = atomicAdd(&s_cnt, 1u);
                cand[idx] = u;
                cidx[idx] = (int)i;
            }
        }
    }
    __syncthreads();
    const unsigned cnt = s_cnt;

    // ---- Round 2: bits [10..20], 2048 bins over candidates ----
    for (int i = tid; i < 2048; i += bdim) hist[i] = 0u;
    __syncthreads();
    for (unsigned i = tid; i < cnt; i += bdim)
        atomicAdd(&hist[(cand[i] >> 10) & 2047u], 1u);
    __syncthreads();
    if (tid < 64) {
        unsigned s = 0;
        #pragma unroll 4
        for (int i = 0; i < 32; ++i) s += hist[tid * 32 + i];
        chunk[tid] = s;
    }
    __syncthreads();
    if (tid == 0) {
        unsigned kth = s_kth;
        int c = 63;
        for (; c > 0; --c) { if (kth <= chunk[c]) break; kth -= chunk[c]; }
        const int base = c * 32;
        int d = 31;
        for (; d > 0; --d) { if (kth <= hist[base + d]) break; kth -= hist[base + d]; }
        s_prefix |= (unsigned)(base + d) << 10;
        s_kth = kth;
    }
    __syncthreads();
    const unsigned mid = (s_prefix >> 10) & 2047u;

    // ---- Round 3: bits [0..9], 1024 bins over matching candidates ----
    for (int i = tid; i < 1024; i += bdim) hist[i] = 0u;
    __syncthreads();
    for (unsigned i = tid; i < cnt; i += bdim) {
        unsigned u = cand[i];
        if (((u >> 10) & 2047u) == mid)
            atomicAdd(&hist[u & 1023u], 1u);
    }
    __syncthreads();
    if (tid < 32) {
        unsigned s = 0;
        #pragma unroll 4
        for (int i = 0; i < 32; ++i) s += hist[tid * 32 + i];
        chunk[tid] = s;
    }
    __syncthreads();
    if (tid == 0) {
        unsigned kth = s_kth;
        int c = 31;
        for (; c > 0; --c) { if (kth <= chunk[c]) break; kth -= chunk[c]; }
        const int base = c * 32;
        int d = 31;
        for (; d > 0; --d) { if (kth <= hist[base + d]) break; kth -= hist[base + d]; }
        s_prefix |= (unsigned)(base + d);
        g_thr[b] = s_prefix;
    }
    __syncthreads();
    const unsigned thr = s_prefix;

    // ---- Append boundary candidates >= thr (padded loop, warp-safe) ----
    {
        const unsigned nloop = ((cnt + bdim - 1) / bdim) * bdim;
        for (unsigned i = tid; i < nloop; i += bdim) {
            const bool valid = (i < cnt);
            const unsigned u = valid ? cand[i] : 0u;
            const int     id = valid ? cidx[i] : 0;
            const float   fv = __uint_as_float(
                u ^ ((u & 0x80000000u) ? 0x80000000u : 0xFFFFFFFFu));
            emit_kept(b, &s_kcnt, lane, valid && (u >= thr), id, fv);
        }
    }
    __syncthreads();
    if (tid == 0) g_kcnt[b] = (s_kcnt < KCAP) ? s_kcnt : KCAP;
}

// ---------------------------------------------------------------------------
// Kernel 3: scatter kept patches (overwrites the zeros). One warp per FOUR
// kept-list slots: 8 independent float4 loads per lane (MLP=8). Also
// re-zeros g_hist for the next graph replay (stream-ordered).
// ---------------------------------------------------------------------------
__global__ void scatter_kernel(const float* __restrict__ x,
                               float* __restrict__ y)
{
    // Re-zero the histogram for the next replay (deterministic state).
    {
        const unsigned t = blockIdx.x * blockDim.x + threadIdx.x;
        if (t < B_ * NHBIN) g_hist[t] = 0u;
    }

    const unsigned w    = (blockIdx.x * blockDim.x + threadIdx.x) >> 5;
    const int lane      = threadIdx.x & 31;
    const unsigned GRP  = KCAP / 4;            // 320 groups per image
    const unsigned img  = w / GRP;
    const unsigned s0   = (w % GRP) * 4;
    if (img >= B_) return;
    const unsigned kc = __ldg(&g_kcnt[img]);
    const int rs = W_ * (C_ / 4);

    bool act[4];
    float sv[4];
    const float4* xr[4];
    float4* yw[4];
    #pragma unroll
    for (int j = 0; j < 4; ++j) {
        const unsigned slot = s0 + j;
        act[j] = slot < kc;
        const unsigned sl = act[j] ? slot : 0u;
        const int p = g_kidx[img * KCAP + sl];
        sv[j] = g_kval[img * KCAP + sl];
        const int ho = p / WO_;
        const int wo = p % WO_;
        const size_t base = (((size_t)img * H_ + 2 * ho) * W_ + 2 * wo) * C_;
        xr[j] = reinterpret_cast<const float4*>(x + base);
        yw[j] = reinterpret_cast<float4*>(y + base);
    }

    float4 a0[4], a1[4];
    #pragma unroll
    for (int j = 0; j < 4; ++j) {
        if (act[j]) {
            a0[j] = __ldg(&xr[j][lane]);
            a1[j] = __ldg(&xr[j][rs + lane]);
        }
    }
    #pragma unroll
    for (int j = 0; j < 4; ++j) {
        if (act[j]) {
            const float v = sv[j];
            a0[j].x *= v; a0[j].y *= v; a0[j].z *= v; a0[j].w *= v;
            a1[j].x *= v; a1[j].y *= v; a1[j].z *= v; a1[j].w *= v;
            __stcs(&yw[j][lane],      a0[j]);
            __stcs(&yw[j][rs + lane], a1[j]);
        }
    }
}

// ---------------------------------------------------------------------------
extern "C" void kernel_launch(void* const* d_in, const int* in_sizes, int n_in,
                              void* d_out, int out_size)
{
    const float* x  = (const float*)d_in[0];   // [16,224,224,64] f32
    const float* wk = (const float*)d_in[1];   // [2,2,64,1] f32
    float* y = (float*)d_out;

    // K1: fused conv + zero-fill + histogram, one warp per 8 patches
    {
        const int warps = TOTPATCH / 8;                           // 25088
        const int threads = 256;
        const int blocks = (warps * 32 + threads - 1) / threads;  // 3136
        conv_zero_kernel<<<blocks, threads>>>(x, wk, y);
    }
    // K2: one block per image — threshold + kept-list compaction
    select_thr_kernel<<<B_, 1024>>>();
    // K3: one warp per 4 kept slots (+ g_hist re-zero)
    {
        const int warps = B_ * (KCAP / 4);                        // 5120
        const int threads = 256;
        const int blocks = warps * 32 / threads;                  // 640
        scatter_kernel<<<blocks, threads>>>(x, y);
    }
}

// round 12
// speedup vs baseline: 1.0201x; 1.0201x over previous
#include <cuda_runtime.h>
#include <cstdint>

// Problem constants
#define B_   16
#define H_   224
#define W_   224
#define C_   64
#define HO_  112
#define WO_  112
#define NPATCH (HO_ * WO_)          // 12544 per image
#define TOTPATCH (B_ * NPATCH)      // 200704
#define KSEL 1254
#define KCAP 1280                   // per-image kept-list capacity (tie slack)

// Scratch (__device__ globals, no allocs)
__device__ float    g_scores[TOTPATCH];   // conv outputs
__device__ unsigned g_thr[B_];            // per-image K-th-largest orderable key
__device__ unsigned g_cand[TOTPATCH];     // boundary-bin candidate keys
__device__ int      g_cidx[TOTPATCH];     // boundary-bin candidate indices
__device__ int      g_kidx[B_ * KCAP];    // kept patch index (within image)
__device__ float    g_kval[B_ * KCAP];    // kept gate value
__device__ unsigned g_kcnt[B_];           // kept count per image

__device__ __forceinline__ unsigned float_orderable(float f)
{
    unsigned u = __float_as_uint(f);
    return u ^ ((u & 0x80000000u) ? 0xFFFFFFFFu : 0x80000000u);
}

// ---------------------------------------------------------------------------
// Kernel 1: fused conv + zero-fill (round-10 known-good version, 59.8us).
// One warp per EIGHT horizontally adjacent patches: reads its 8 KB x tile,
// streams 8 KB of zeros into y (scatter overwrites kept patches later).
// ---------------------------------------------------------------------------
__global__ void conv_zero_kernel(const float* __restrict__ x,
                                 const float* __restrict__ wk,
                                 float* __restrict__ y)
{
    if (blockIdx.x == 0 && threadIdx.x < B_) g_kcnt[threadIdx.x] = 0u;

    const unsigned warp = (blockIdx.x * blockDim.x + threadIdx.x) >> 5;
    const int lane = threadIdx.x & 31;
    const unsigned p0 = warp * 8;               // first patch of this group
    if (p0 >= TOTPATCH) return;

    const int b   = p0 / NPATCH;
    const int rem = p0 % NPATCH;
    const int ho  = rem / WO_;
    const int wo  = rem % WO_;                  // multiple of 8

    const size_t base = (((size_t)b * H_ + 2 * ho) * W_ + 2 * wo) * C_;
    const float4* xr = reinterpret_cast<const float4*>(x + base);
    float4*       yr = reinterpret_cast<float4*>(y + base);
    const float4* wr = reinterpret_cast<const float4*>(wk);
    const int rs = W_ * (C_ / 4);               // row stride in float4

    const float4 w0 = __ldg(&wr[lane]);
    const float4 w1 = __ldg(&wr[32 + lane]);

    // Issue all 16 loads first (max MLP), then the 16 zero stores.
    float4 a0[8], a1[8];
    #pragma unroll
    for (int j = 0; j < 8; ++j) a0[j] = __ldcs(&xr[32 * j + lane]);
    #pragma unroll
    for (int j = 0; j < 8; ++j) a1[j] = __ldcs(&xr[rs + 32 * j + lane]);

    const float4 z = make_float4(0.f, 0.f, 0.f, 0.f);
    #pragma unroll
    for (int j = 0; j < 8; ++j) __stcs(&yr[32 * j + lane], z);
    #pragma unroll
    for (int j = 0; j < 8; ++j) __stcs(&yr[rs + 32 * j + lane], z);

    float s[8];
    #pragma unroll
    for (int j = 0; j < 8; ++j) {
        s[j] = a0[j].x * w0.x + a0[j].y * w0.y + a0[j].z * w0.z + a0[j].w * w0.w
             + a1[j].x * w1.x + a1[j].y * w1.y + a1[j].z * w1.z + a1[j].w * w1.w;
    }

    #pragma unroll
    for (int j = 0; j < 8; ++j) {
        #pragma unroll
        for (int off = 16; off; off >>= 1)
            s[j] += __shfl_down_sync(0xffffffffu, s[j], off);
    }

    if (lane == 0) {
        *reinterpret_cast<float4*>(&g_scores[p0])     = make_float4(s[0], s[1], s[2], s[3]);
        *reinterpret_cast<float4*>(&g_scores[p0 + 4]) = make_float4(s[4], s[5], s[6], s[7]);
    }
}

// ---------------------------------------------------------------------------
// Kernel 2: per-image K-th-largest threshold via radix select + kept-list
// compaction (the 86.4us config). Loops containing warp-collective emit_kept
// are padded to a multiple of blockDim.x with a validity predicate.
// ---------------------------------------------------------------------------

// All 32 lanes of the warp MUST call this (kept=false for inactive work).
__device__ __forceinline__ void emit_kept(int b, unsigned* s_kcnt,
                                          int lane, bool kept, int idx, float val)
{
    const unsigned m = __ballot_sync(0xffffffffu, kept);
    if (kept) {
        const int leader = __ffs(m) - 1;
        unsigned basep = 0;
        if (lane == leader) basep = atomicAdd(s_kcnt, (unsigned)__popc(m));
        basep = __shfl_sync(m, basep, leader);
        const unsigned slot = basep + __popc(m & ((1u << lane) - 1u));
        if (slot < KCAP) {
            g_kidx[b * KCAP + slot] = idx;
            g_kval[b * KCAP + slot] = val;
        }
    }
}

__global__ void select_thr_kernel()
{
    __shared__ unsigned hist[2048];
    __shared__ unsigned chunk[64];
    __shared__ unsigned s_prefix, s_kth, s_cnt, s_kcnt;

    const int b    = blockIdx.x;
    const int tid  = threadIdx.x;
    const int lane = tid & 31;
    const unsigned bdim = blockDim.x;
    const float* gb = g_scores + (size_t)b * NPATCH;
    unsigned* cand = g_cand + (size_t)b * NPATCH;
    int*      cidx = g_cidx + (size_t)b * NPATCH;

    if (tid == 0) { s_cnt = 0u; s_kcnt = 0u; }

    // ---- Round 1: full scan, 2048 bins over bits [21..31] ----
    for (int i = tid; i < 2048; i += bdim) hist[i] = 0u;
    __syncthreads();
    for (int i = tid; i < NPATCH; i += bdim) {
        unsigned u = float_orderable(gb[i]);
        atomicAdd(&hist[u >> 21], 1u);
    }
    __syncthreads();
    if (tid < 64) {
        unsigned s = 0;
        #pragma unroll 4
        for (int i = 0; i < 32; ++i) s += hist[tid * 32 + i];
        chunk[tid] = s;
    }
    __syncthreads();
    if (tid == 0) {
        unsigned kth = KSEL;
        int c = 63;
        for (; c > 0; --c) { if (kth <= chunk[c]) break; kth -= chunk[c]; }
        const int base = c * 32;
        int d = 31;
        for (; d > 0; --d) { if (kth <= hist[base + d]) break; kth -= hist[base + d]; }
        s_prefix = (unsigned)(base + d) << 21;
        s_kth = kth;
    }
    __syncthreads();
    const unsigned top = s_prefix >> 21;

    // ---- Compaction pass: definite keeps + boundary candidates ----
    {
        const unsigned nloop = ((NPATCH + bdim - 1) / bdim) * bdim;
        for (unsigned i = tid; i < nloop; i += bdim) {
            const bool valid = (i < NPATCH);
            const float f = valid ? gb[i] : 0.0f;
            const unsigned u = float_orderable(f);
            const unsigned bin = u >> 21;
            emit_kept(b, &s_kcnt, lane, valid && (bin > top), (int)i, f);
            if (valid && bin == top) {
                unsigned idx = atomicAdd(&s_cnt, 1u);
                cand[idx] = u;
                cidx[idx] = (int)i;
            }
        }
    }
    __syncthreads();
    const unsigned cnt = s_cnt;

    // ---- Round 2: bits [10..20], 2048 bins over candidates ----
    for (int i = tid; i < 2048; i += bdim) hist[i] = 0u;
    __syncthreads();
    for (unsigned i = tid; i < cnt; i += bdim)
        atomicAdd(&hist[(cand[i] >> 10) & 2047u], 1u);
    __syncthreads();
    if (tid < 64) {
        unsigned s = 0;
        #pragma unroll 4
        for (int i = 0; i < 32; ++i) s += hist[tid * 32 + i];
        chunk[tid] = s;
    }
    __syncthreads();
    if (tid == 0) {
        unsigned kth = s_kth;
        int c = 63;
        for (; c > 0; --c) { if (kth <= chunk[c]) break; kth -= chunk[c]; }
        const int base = c * 32;
        int d = 31;
        for (; d > 0; --d) { if (kth <= hist[base + d]) break; kth -= hist[base + d]; }
        s_prefix |= (unsigned)(base + d) << 10;
        s_kth = kth;
    }
    __syncthreads();
    const unsigned mid = (s_prefix >> 10) & 2047u;

    // ---- Round 3: bits [0..9], 1024 bins over matching candidates ----
    for (int i = tid; i < 1024; i += bdim) hist[i] = 0u;
    __syncthreads();
    for (unsigned i = tid; i < cnt; i += bdim) {
        unsigned u = cand[i];
        if (((u >> 10) & 2047u) == mid)
            atomicAdd(&hist[u & 1023u], 1u);
    }
    __syncthreads();
    if (tid < 32) {
        unsigned s = 0;
        #pragma unroll 4
        for (int i = 0; i < 32; ++i) s += hist[tid * 32 + i];
        chunk[tid] = s;
    }
    __syncthreads();
    if (tid == 0) {
        unsigned kth = s_kth;
        int c = 31;
        for (; c > 0; --c) { if (kth <= chunk[c]) break; kth -= chunk[c]; }
        const int base = c * 32;
        int d = 31;
        for (; d > 0; --d) { if (kth <= hist[base + d]) break; kth -= hist[base + d]; }
        s_prefix |= (unsigned)(base + d);
        g_thr[b] = s_prefix;
    }
    __syncthreads();
    const unsigned thr = s_prefix;

    // ---- Append boundary candidates >= thr (padded loop, warp-safe) ----
    {
        const unsigned nloop = ((cnt + bdim - 1) / bdim) * bdim;
        for (unsigned i = tid; i < nloop; i += bdim) {
            const bool valid = (i < cnt);
            const unsigned u = valid ? cand[i] : 0u;
            const int     id = valid ? cidx[i] : 0;
            const float   fv = __uint_as_float(
                u ^ ((u & 0x80000000u) ? 0x80000000u : 0xFFFFFFFFu));
            emit_kept(b, &s_kcnt, lane, valid && (u >= thr), id, fv);
        }
    }
    __syncthreads();
    if (tid == 0) g_kcnt[b] = (s_kcnt < KCAP) ? s_kcnt : KCAP;
}

// ---------------------------------------------------------------------------
// Kernel 3: scatter kept patches (overwrites the zeros). One warp per TWO
// kept-list slots with EXPLICIT scalar variables (no indexed arrays -> low
// register pressure, no spills). MLP=4 independent loads per lane.
// ---------------------------------------------------------------------------
__global__ void scatter_kernel(const float* __restrict__ x,
                               float* __restrict__ y)
{
    const unsigned w    = (blockIdx.x * blockDim.x + threadIdx.x) >> 5;
    const int lane      = threadIdx.x & 31;
    const unsigned GRP  = KCAP / 2;            // 640 groups per image
    const unsigned img  = w / GRP;
    const unsigned s0   = (w % GRP) * 2;
    if (img >= B_) return;
    const unsigned kc = __ldg(&g_kcnt[img]);
    const int rs = W_ * (C_ / 4);

    const bool act0 = (s0     < kc);
    const bool act1 = (s0 + 1 < kc);

    const unsigned sl0 = act0 ? s0     : 0u;
    const unsigned sl1 = act1 ? s0 + 1 : 0u;

    const int   p0v = g_kidx[img * KCAP + sl0];
    const float v0  = g_kval[img * KCAP + sl0];
    const int   p1v = g_kidx[img * KCAP + sl1];
    const float v1  = g_kval[img * KCAP + sl1];

    const size_t base0 = (((size_t)img * H_ + 2 * (p0v / WO_)) * W_ + 2 * (p0v % WO_)) * C_;
    const size_t base1 = (((size_t)img * H_ + 2 * (p1v / WO_)) * W_ + 2 * (p1v % WO_)) * C_;

    const float4* xr0 = reinterpret_cast<const float4*>(x + base0);
    const float4* xr1 = reinterpret_cast<const float4*>(x + base1);
    float4* yw0 = reinterpret_cast<float4*>(y + base0);
    float4* yw1 = reinterpret_cast<float4*>(y + base1);

    float4 a00, a01, a10, a11;
    if (act0) { a00 = __ldg(&xr0[lane]); a01 = __ldg(&xr0[rs + lane]); }
    if (act1) { a10 = __ldg(&xr1[lane]); a11 = __ldg(&xr1[rs + lane]); }

    if (act0) {
        a00.x *= v0; a00.y *= v0; a00.z *= v0; a00.w *= v0;
        a01.x *= v0; a01.y *= v0; a01.z *= v0; a01.w *= v0;
        __stcs(&yw0[lane],      a00);
        __stcs(&yw0[rs + lane], a01);
    }
    if (act1) {
        a10.x *= v1; a10.y *= v1; a10.z *= v1; a10.w *= v1;
        a11.x *= v1; a11.y *= v1; a11.z *= v1; a11.w *= v1;
        __stcs(&yw1[lane],      a10);
        __stcs(&yw1[rs + lane], a11);
    }
}

// ---------------------------------------------------------------------------
extern "C" void kernel_launch(void* const* d_in, const int* in_sizes, int n_in,
                              void* d_out, int out_size)
{
    const float* x  = (const float*)d_in[0];   // [16,224,224,64] f32
    const float* wk = (const float*)d_in[1];   // [2,2,64,1] f32
    float* y = (float*)d_out;

    // K1: fused conv + zero-fill, one warp per 8 patches
    {
        const int warps = TOTPATCH / 8;                           // 25088
        const int threads = 256;
        const int blocks = (warps * 32 + threads - 1) / threads;  // 3136
        conv_zero_kernel<<<blocks, threads>>>(x, wk, y);
    }
    // K2: one block per image — threshold + kept-list compaction
    select_thr_kernel<<<B_, 1024>>>();
    // K3: one warp per 2 kept slots
    {
        const int warps = B_ * (KCAP / 2);                        // 10240
        const int threads = 256;
        const int blocks = warps * 32 / threads;                  // 1280
        scatter_kernel<<<blocks, threads>>>(x, y);
    }
}

// round 13
// speedup vs baseline: 1.2428x; 1.2183x over previous
#include <cuda_runtime.h>
#include <cstdint>

// Problem constants
#define B_   16
#define H_   224
#define W_   224
#define C_   64
#define HO_  112
#define WO_  112
#define NPATCH (HO_ * WO_)          // 12544 per image
#define TOTPATCH (B_ * NPATCH)      // 200704
#define KSEL 1254
#define KCAP 1280                   // per-image kept-list capacity (tie slack)

// Scratch (__device__ globals, no allocs)
__device__ float    g_scores[TOTPATCH];   // conv outputs
__device__ unsigned g_thr[B_];            // per-image K-th-largest orderable key
__device__ unsigned g_cand[TOTPATCH];     // boundary-bin candidate keys
__device__ int      g_cidx[TOTPATCH];     // boundary-bin candidate indices
__device__ int      g_kidx[B_ * KCAP];    // kept patch index (within image)
__device__ float    g_kval[B_ * KCAP];    // kept gate value
__device__ unsigned g_kcnt[B_];           // kept count per image

__device__ __forceinline__ unsigned float_orderable(float f)
{
    unsigned u = __float_as_uint(f);
    return u ^ ((u & 0x80000000u) ? 0xFFFFFFFFu : 0x80000000u);
}

// ---------------------------------------------------------------------------
// Kernel 1: fused conv + zero-fill (round-10 measured-best: 59.8us). One warp
// per EIGHT horizontally adjacent patches: reads its 8 KB x tile, streams
// 8 KB of zeros into y (scatter overwrites kept patches later).
// ---------------------------------------------------------------------------
__global__ void conv_zero_kernel(const float* __restrict__ x,
                                 const float* __restrict__ wk,
                                 float* __restrict__ y)
{
    if (blockIdx.x == 0 && threadIdx.x < B_) g_kcnt[threadIdx.x] = 0u;

    const unsigned warp = (blockIdx.x * blockDim.x + threadIdx.x) >> 5;
    const int lane = threadIdx.x & 31;
    const unsigned p0 = warp * 8;               // first patch of this group
    if (p0 >= TOTPATCH) return;

    const int b   = p0 / NPATCH;
    const int rem = p0 % NPATCH;
    const int ho  = rem / WO_;
    const int wo  = rem % WO_;                  // multiple of 8

    const size_t base = (((size_t)b * H_ + 2 * ho) * W_ + 2 * wo) * C_;
    const float4* xr = reinterpret_cast<const float4*>(x + base);
    float4*       yr = reinterpret_cast<float4*>(y + base);
    const float4* wr = reinterpret_cast<const float4*>(wk);
    const int rs = W_ * (C_ / 4);               // row stride in float4

    const float4 w0 = __ldg(&wr[lane]);
    const float4 w1 = __ldg(&wr[32 + lane]);

    // Issue all 16 loads first (max MLP), then the 16 zero stores.
    float4 a0[8], a1[8];
    #pragma unroll
    for (int j = 0; j < 8; ++j) a0[j] = __ldcs(&xr[32 * j + lane]);
    #pragma unroll
    for (int j = 0; j < 8; ++j) a1[j] = __ldcs(&xr[rs + 32 * j + lane]);

    const float4 z = make_float4(0.f, 0.f, 0.f, 0.f);
    #pragma unroll
    for (int j = 0; j < 8; ++j) __stcs(&yr[32 * j + lane], z);
    #pragma unroll
    for (int j = 0; j < 8; ++j) __stcs(&yr[rs + 32 * j + lane], z);

    float s[8];
    #pragma unroll
    for (int j = 0; j < 8; ++j) {
        s[j] = a0[j].x * w0.x + a0[j].y * w0.y + a0[j].z * w0.z + a0[j].w * w0.w
             + a1[j].x * w1.x + a1[j].y * w1.y + a1[j].z * w1.z + a1[j].w * w1.w;
    }

    #pragma unroll
    for (int j = 0; j < 8; ++j) {
        #pragma unroll
        for (int off = 16; off; off >>= 1)
            s[j] += __shfl_down_sync(0xffffffffu, s[j], off);
    }

    if (lane == 0) {
        *reinterpret_cast<float4*>(&g_scores[p0])     = make_float4(s[0], s[1], s[2], s[3]);
        *reinterpret_cast<float4*>(&g_scores[p0 + 4]) = make_float4(s[4], s[5], s[6], s[7]);
    }
}

// ---------------------------------------------------------------------------
// Kernel 2: per-image K-th-largest threshold via radix select + kept-list
// compaction. Round 1 uses 4096 bins (bits 20-31) to spread Gaussian-score
// exponent concentration across more smem-atomic addresses and shrink the
// boundary-candidate set. Rounds: 12/11/9 bits.
// Loops containing warp-collective emit_kept are padded to blockDim.x.
// ---------------------------------------------------------------------------

// All 32 lanes of the warp MUST call this (kept=false for inactive work).
__device__ __forceinline__ void emit_kept(int b, unsigned* s_kcnt,
                                          int lane, bool kept, int idx, float val)
{
    const unsigned m = __ballot_sync(0xffffffffu, kept);
    if (kept) {
        const int leader = __ffs(m) - 1;
        unsigned basep = 0;
        if (lane == leader) basep = atomicAdd(s_kcnt, (unsigned)__popc(m));
        basep = __shfl_sync(m, basep, leader);
        const unsigned slot = basep + __popc(m & ((1u << lane) - 1u));
        if (slot < KCAP) {
            g_kidx[b * KCAP + slot] = idx;
            g_kval[b * KCAP + slot] = val;
        }
    }
}

__global__ void select_thr_kernel()
{
    __shared__ unsigned hist[4096];
    __shared__ unsigned chunk[128];
    __shared__ unsigned s_prefix, s_kth, s_cnt, s_kcnt;

    const int b    = blockIdx.x;
    const int tid  = threadIdx.x;
    const int lane = tid & 31;
    const unsigned bdim = blockDim.x;
    const float* gb = g_scores + (size_t)b * NPATCH;
    unsigned* cand = g_cand + (size_t)b * NPATCH;
    int*      cidx = g_cidx + (size_t)b * NPATCH;

    if (tid == 0) { s_cnt = 0u; s_kcnt = 0u; }

    // ---- Round 1: full scan, 4096 bins over bits [20..31] ----
    for (int i = tid; i < 4096; i += bdim) hist[i] = 0u;
    __syncthreads();
    for (int i = tid; i < NPATCH; i += bdim) {
        unsigned u = float_orderable(gb[i]);
        atomicAdd(&hist[u >> 20], 1u);
    }
    __syncthreads();
    if (tid < 128) {
        unsigned s = 0;
        #pragma unroll 4
        for (int i = 0; i < 32; ++i) s += hist[tid * 32 + i];
        chunk[tid] = s;
    }
    __syncthreads();
    if (tid == 0) {
        unsigned kth = KSEL;
        int c = 127;
        for (; c > 0; --c) { if (kth <= chunk[c]) break; kth -= chunk[c]; }
        const int base = c * 32;
        int d = 31;
        for (; d > 0; --d) { if (kth <= hist[base + d]) break; kth -= hist[base + d]; }
        s_prefix = (unsigned)(base + d) << 20;
        s_kth = kth;
    }
    __syncthreads();
    const unsigned top = s_prefix >> 20;

    // ---- Compaction pass: definite keeps + boundary candidates ----
    {
        const unsigned nloop = ((NPATCH + bdim - 1) / bdim) * bdim;
        for (unsigned i = tid; i < nloop; i += bdim) {
            const bool valid = (i < NPATCH);
            const float f = valid ? gb[i] : 0.0f;
            const unsigned u = float_orderable(f);
            const unsigned bin = u >> 20;
            emit_kept(b, &s_kcnt, lane, valid && (bin > top), (int)i, f);
            if (valid && bin == top) {
                unsigned idx = atomicAdd(&s_cnt, 1u);
                cand[idx] = u;
                cidx[idx] = (int)i;
            }
        }
    }
    __syncthreads();
    const unsigned cnt = s_cnt;

    // ---- Round 2: bits [9..19], 2048 bins over candidates ----
    for (int i = tid; i < 2048; i += bdim) hist[i] = 0u;
    __syncthreads();
    for (unsigned i = tid; i < cnt; i += bdim)
        atomicAdd(&hist[(cand[i] >> 9) & 2047u], 1u);
    __syncthreads();
    if (tid < 64) {
        unsigned s = 0;
        #pragma unroll 4
        for (int i = 0; i < 32; ++i) s += hist[tid * 32 + i];
        chunk[tid] = s;
    }
    __syncthreads();
    if (tid == 0) {
        unsigned kth = s_kth;
        int c = 63;
        for (; c > 0; --c) { if (kth <= chunk[c]) break; kth -= chunk[c]; }
        const int base = c * 32;
        int d = 31;
        for (; d > 0; --d) { if (kth <= hist[base + d]) break; kth -= hist[base + d]; }
        s_prefix |= (unsigned)(base + d) << 9;
        s_kth = kth;
    }
    __syncthreads();
    const unsigned mid = (s_prefix >> 9) & 2047u;

    // ---- Round 3: bits [0..8], 512 bins over matching candidates ----
    for (int i = tid; i < 512; i += bdim) hist[i] = 0u;
    __syncthreads();
    for (unsigned i = tid; i < cnt; i += bdim) {
        unsigned u = cand[i];
        if (((u >> 9) & 2047u) == mid)
            atomicAdd(&hist[u & 511u], 1u);
    }
    __syncthreads();
    if (tid < 16) {
        unsigned s = 0;
        #pragma unroll 4
        for (int i = 0; i < 32; ++i) s += hist[tid * 32 + i];
        chunk[tid] = s;
    }
    __syncthreads();
    if (tid == 0) {
        unsigned kth = s_kth;
        int c = 15;
        for (; c > 0; --c) { if (kth <= chunk[c]) break; kth -= chunk[c]; }
        const int base = c * 32;
        int d = 31;
        for (; d > 0; --d) { if (kth <= hist[base + d]) break; kth -= hist[base + d]; }
        s_prefix |= (unsigned)(base + d);
        g_thr[b] = s_prefix;
    }
    __syncthreads();
    const unsigned thr = s_prefix;

    // ---- Append boundary candidates >= thr (padded loop, warp-safe) ----
    {
        const unsigned nloop = ((cnt + bdim - 1) / bdim) * bdim;
        for (unsigned i = tid; i < nloop; i += bdim) {
            const bool valid = (i < cnt);
            const unsigned u = valid ? cand[i] : 0u;
            const int     id = valid ? cidx[i] : 0;
            const float   fv = __uint_as_float(
                u ^ ((u & 0x80000000u) ? 0x80000000u : 0xFFFFFFFFu));
            emit_kept(b, &s_kcnt, lane, valid && (u >= thr), id, fv);
        }
    }
    __syncthreads();
    if (tid == 0) g_kcnt[b] = (s_kcnt < KCAP) ? s_kcnt : KCAP;
}

// ---------------------------------------------------------------------------
// Kernel 3: scatter kept patches (overwrites the zeros). Round-6 measured
// version (11.2us): one warp per kept-list slot, 2 rows x 512 B per patch.
// ---------------------------------------------------------------------------
__global__ void scatter_kernel(const float* __restrict__ x,
                               float* __restrict__ y)
{
    const unsigned w    = (blockIdx.x * blockDim.x + threadIdx.x) >> 5;
    const int lane      = threadIdx.x & 31;
    const unsigned img  = w / KCAP;
    const unsigned slot = w % KCAP;
    if (img >= B_ || slot >= __ldg(&g_kcnt[img])) return;

    const int   p   = g_kidx[img * KCAP + slot];
    const float val = g_kval[img * KCAP + slot];
    const int ho = p / WO_;
    const int wo = p % WO_;

    const size_t base = (((size_t)img * H_ + 2 * ho) * W_ + 2 * wo) * C_;
    const int rs = W_ * (C_ / 4);
    const float4* xr = reinterpret_cast<const float4*>(x + base);
    float4*       yr = reinterpret_cast<float4*>(y + base);

    float4 v0 = __ldg(&xr[lane]);
    float4 v1 = __ldg(&xr[rs + lane]);
    v0.x *= val; v0.y *= val; v0.z *= val; v0.w *= val;
    v1.x *= val; v1.y *= val; v1.z *= val; v1.w *= val;
    __stcs(&yr[lane],      v0);
    __stcs(&yr[rs + lane], v1);
}

// ---------------------------------------------------------------------------
extern "C" void kernel_launch(void* const* d_in, const int* in_sizes, int n_in,
                              void* d_out, int out_size)
{
    const float* x  = (const float*)d_in[0];   // [16,224,224,64] f32
    const float* wk = (const float*)d_in[1];   // [2,2,64,1] f32
    float* y = (float*)d_out;

    // K1: fused conv + zero-fill, one warp per 8 patches
    {
        const int warps = TOTPATCH / 8;                           // 25088
        const int threads = 256;
        const int blocks = (warps * 32 + threads - 1) / threads;  // 3136
        conv_zero_kernel<<<blocks, threads>>>(x, wk, y);
    }
    // K2: one block per image — threshold + kept-list compaction
    select_thr_kernel<<<B_, 1024>>>();
    // K3: one warp per kept slot
    {
        const int warps = B_ * KCAP;                              // 20480
        const int threads = 256;
        const int blocks = warps * 32 / threads;                  // 2560
        scatter_kernel<<<blocks, threads>>>(x, y);
    }
}